// round 1
// baseline (speedup 1.0000x reference)
#include <cuda_runtime.h>

// Problem constants (from reference):
// B=8192, L=64, Cin=8, KS=4, trunc=9, Lo=55, Caug=11, DEPTH=3
// sig channels: 11 + 121 + 1331 = 1463 ; head: 1463 -> 10
#define WARPS   4
#define NTHREADS (32 * WARPS)
#define LFULL   64
#define CIN     8
#define LO      55
#define CC      11
#define CC2     121
#define SIGCH   1463
#define NSTOCK  10

struct WarpSmem {
    float xs[8 * 64];    // x transposed: [c][t]
    float h1[8 * 64];    // relu(conv1) [o][t], t<61
    float h2[8 * 64];    // relu(conv2) [o][t], t<58
    float h3[2 * 56];    // conv3 (no relu) [o][t], t<55
    float dxs[55 * 12];  // increments [t][c], c<11 (col 11 = pad)
};

__global__ void __launch_bounds__(NTHREADS)
deepsig_kernel(const float* __restrict__ x,
               const float* __restrict__ W1, const float* __restrict__ b1,
               const float* __restrict__ W2, const float* __restrict__ b2,
               const float* __restrict__ W3, const float* __restrict__ b3,
               const float* __restrict__ Wl, const float* __restrict__ bl,
               float* __restrict__ out, int B)
{
    __shared__ WarpSmem ws[WARPS];
    __shared__ float w1s[256], w2s[256], w3s[64], b1s[8], b2s[8], b3s[2];

    const int tid  = threadIdx.x;
    const int warp = tid >> 5;
    const int lane = tid & 31;

    // Block-cooperative load of tiny conv weights into shared
    for (int i = tid; i < 256; i += NTHREADS) { w1s[i] = W1[i]; w2s[i] = W2[i]; }
    for (int i = tid; i < 64;  i += NTHREADS) { w3s[i] = W3[i]; }
    if (tid < 8) { b1s[tid] = b1[tid]; b2s[tid] = b2[tid]; }
    if (tid < 2) { b3s[tid] = b3[tid]; }
    __syncthreads();

    const int b = blockIdx.x * WARPS + warp;
    if (b >= B) return;

    WarpSmem& S = ws[warp];

    // ---- Load x (coalesced), transpose into shared [c][t] ----
    const float* xb = x + (size_t)b * (LFULL * CIN);
    for (int i = lane; i < LFULL * CIN; i += 32) {
        int t = i >> 3, c = i & 7;
        S.xs[c * 64 + t] = xb[i];
    }
    __syncwarp();

    // ---- conv1 (VALID, KS=4) + relu : out [8][61] ----
    for (int idx = lane; idx < 8 * 61; idx += 32) {
        int o = idx / 61, t = idx - o * 61;
        float acc = b1s[o];
        #pragma unroll
        for (int i = 0; i < 8; i++)
            #pragma unroll
            for (int k = 0; k < 4; k++)
                acc = fmaf(S.xs[i * 64 + t + k], w1s[(o * 8 + i) * 4 + k], acc);
        S.h1[o * 64 + t] = fmaxf(acc, 0.0f);
    }
    __syncwarp();

    // ---- conv2 + relu : out [8][58] ----
    for (int idx = lane; idx < 8 * 58; idx += 32) {
        int o = idx / 58, t = idx - o * 58;
        float acc = b2s[o];
        #pragma unroll
        for (int i = 0; i < 8; i++)
            #pragma unroll
            for (int k = 0; k < 4; k++)
                acc = fmaf(S.h1[i * 64 + t + k], w2s[(o * 8 + i) * 4 + k], acc);
        S.h2[o * 64 + t] = fmaxf(acc, 0.0f);
    }
    __syncwarp();

    // ---- conv3 (NO relu) : out [2][55] ----
    for (int idx = lane; idx < 2 * 55; idx += 32) {
        int o = idx / 55, t = idx - o * 55;
        float acc = b3s[o];
        #pragma unroll
        for (int i = 0; i < 8; i++)
            #pragma unroll
            for (int k = 0; k < 4; k++)
                acc = fmaf(S.h2[i * 64 + t + k], w3s[(o * 8 + i) * 4 + k], acc);
        S.h3[o * 56 + t] = acc;
    }
    __syncwarp();

    // ---- Path increments dx[t][c], t=0..54, c=0..10 ----
    // path[t] = [ x[9+t][0..7], t/54, h3[0][t], h3[1][t] ], dx[0] = path[0]
    for (int idx = lane; idx < 55 * 11; idx += 32) {
        int t = idx / 11, c = idx - t * 11;
        float v;
        if (c < 8) {
            v = (t == 0) ? S.xs[c * 64 + 9]
                         : S.xs[c * 64 + 9 + t] - S.xs[c * 64 + 8 + t];
        } else if (c == 8) {
            v = (t == 0) ? 0.0f : (1.0f / 54.0f);
        } else {
            int o = c - 9;
            v = (t == 0) ? S.h3[o * 56]
                         : S.h3[o * 56 + t] - S.h3[o * 56 + t - 1];
        }
        S.dxs[t * 12 + c] = v;
    }
    __syncwarp();

    // ---- Signature main loop (Chen relation, factored) ----
    // Lane owns ij = lane + 32*m (m = 0..3), ij < 121.
    // sig2[ij] += (sig1[i] + dx[i]/2) * dx[j]
    // M[ij]     = sig2_old[ij] + (sig1_old[i]/2 + dx[i]/6) * dx[j]
    // sig3[ij][k] += M[ij] * dx[k]
    int ijm[4], im[4], jm[4];
    bool valid3 = (lane + 96) < CC2;   // lanes 0..24 own a 4th pair
    #pragma unroll
    for (int m = 0; m < 4; m++) {
        int ij = lane + 32 * m;
        if (ij >= CC2) ij = 0;         // clamp (guarded out of compute anyway)
        ijm[m] = ij; im[m] = ij / 11; jm[m] = ij - (ij / 11) * 11;
    }

    float s1i[4] = {0.f, 0.f, 0.f, 0.f};
    float s2[4]  = {0.f, 0.f, 0.f, 0.f};
    float s3[4][11];
    #pragma unroll
    for (int m = 0; m < 4; m++)
        #pragma unroll
        for (int k = 0; k < 11; k++) s3[m][k] = 0.0f;

    for (int t = 0; t < LO; t++) {
        const float* row = &S.dxs[t * 12];
        float d[11];
        #pragma unroll
        for (int c = 0; c < 11; c++) d[c] = row[c];

        #pragma unroll
        for (int m = 0; m < 4; m++) {
            if (m < 3 || valid3) {
                float di = row[im[m]];
                float dj = row[jm[m]];
                float Mv = fmaf(dj, fmaf(1.0f / 6.0f, di, 0.5f * s1i[m]), s2[m]);
                s2[m]    = fmaf(dj, fmaf(0.5f, di, s1i[m]), s2[m]);
                s1i[m]  += di;
                #pragma unroll
                for (int k = 0; k < 11; k++)
                    s3[m][k] = fmaf(Mv, d[k], s3[m][k]);
            }
        }
    }

    // ---- Fused linear head: out[b][s] = sum_c sig[c]*Wl[s][c] + bl[s] ----
    float acc[NSTOCK];
    #pragma unroll
    for (int s = 0; s < NSTOCK; s++) acc[s] = 0.0f;

    // sig1 = path[54] (telescoping sum of increments); lanes 0..10 contribute
    if (lane < CC) {
        float v;
        if (lane < 8)      v = S.xs[lane * 64 + 63];
        else if (lane == 8) v = 1.0f;
        else               v = S.h3[(lane - 9) * 56 + 54];
        #pragma unroll
        for (int s = 0; s < NSTOCK; s++)
            acc[s] = v * __ldg(&Wl[s * SIGCH + lane]);
    }

    #pragma unroll
    for (int m = 0; m < 4; m++) {
        if (m < 3 || valid3) {
            int ij = ijm[m];
            const float* w2p = Wl + (CC + ij);           // sig2 channel offset
            #pragma unroll
            for (int s = 0; s < NSTOCK; s++)
                acc[s] = fmaf(s2[m], __ldg(&w2p[s * SIGCH]), acc[s]);
            const float* w3p = Wl + (CC + CC2 + ij * 11); // sig3 channel offset
            #pragma unroll
            for (int k = 0; k < 11; k++) {
                float v = s3[m][k];
                #pragma unroll
                for (int s = 0; s < NSTOCK; s++)
                    acc[s] = fmaf(v, __ldg(&w3p[s * SIGCH + k]), acc[s]);
            }
        }
    }

    // warp reduction + write
    #pragma unroll
    for (int s = 0; s < NSTOCK; s++) {
        float v = acc[s];
        #pragma unroll
        for (int off = 16; off > 0; off >>= 1)
            v += __shfl_xor_sync(0xffffffffu, v, off);
        if (lane == 0)
            out[b * NSTOCK + s] = v + __ldg(&bl[s]);
    }
}

extern "C" void kernel_launch(void* const* d_in, const int* in_sizes, int n_in,
                              void* d_out, int out_size)
{
    const float* x  = (const float*)d_in[0];
    const float* W1 = (const float*)d_in[1];
    const float* b1 = (const float*)d_in[2];
    const float* W2 = (const float*)d_in[3];
    const float* b2 = (const float*)d_in[4];
    const float* W3 = (const float*)d_in[5];
    const float* b3 = (const float*)d_in[6];
    const float* Wl = (const float*)d_in[7];
    const float* bl = (const float*)d_in[8];
    float* out = (float*)d_out;

    int B = in_sizes[0] / (LFULL * CIN);   // 8192
    int blocks = (B + WARPS - 1) / WARPS;

    deepsig_kernel<<<blocks, NTHREADS>>>(x, W1, b1, W2, b2, W3, b3, Wl, bl, out, B);
}

// round 2
// speedup vs baseline: 1.7953x; 1.7953x over previous
#include <cuda_runtime.h>

// B=8192, L=64, Cin=8, KS=4, trunc=9, Lo=55, Caug=11, DEPTH=3
// sig = 11 + 121 + 1331 = 1463 channels; head 1463 -> 10
#define WARPS    4
#define NTHREADS (32 * WARPS)
#define LFULL    64
#define CIN      8
#define LO       55
#define CC       11
#define CC2      121
#define SIGCH    1463
#define NSTOCK   10

// per-warp shared region (floats), rows padded to 65 to avoid bank conflicts
#define WROW     65
#define XS_OFF   0               // x transposed [c][t], 8*65
#define H1_OFF   520             // conv1 out, 8*65
#define H2_OFF   1040            // conv2 out, 8*65
#define H3_OFF   1560            // conv3 out, 2*56
#define DXS_OFF  520             // aliases H1/H2 (dead after conv3), 55*12
#define SIG_OFF  0               // aliases XS+H1 after main loop, 1463
#define WARP_FLTS 1680           // padded, keeps 16B alignment

__global__ void __launch_bounds__(NTHREADS)
deepsig_kernel(const float* __restrict__ x,
               const float* __restrict__ W1, const float* __restrict__ b1,
               const float* __restrict__ W2, const float* __restrict__ b2,
               const float* __restrict__ W3, const float* __restrict__ b3,
               const float* __restrict__ Wl, const float* __restrict__ bl,
               float* __restrict__ out, int B)
{
    __shared__ __align__(16) float wmem[WARPS * WARP_FLTS];
    __shared__ float w1s[256], w2s[256], w3s[64], b1s[8], b2s[8], b3s[2];

    const int tid  = threadIdx.x;
    const int warp = tid >> 5;
    const int lane = tid & 31;

    // Stage conv weights transposed: ws[(i*4+k)*OC + o] = W[o][i][k]
    for (int i = tid; i < 256; i += NTHREADS) {
        int o = i >> 5, r = i & 31;
        w1s[r * 8 + o] = W1[i];
        w2s[r * 8 + o] = W2[i];
    }
    for (int i = tid; i < 64; i += NTHREADS) {
        int o = i >> 5, r = i & 31;
        w3s[r * 2 + o] = W3[i];
    }
    if (tid < 8) { b1s[tid] = b1[tid]; b2s[tid] = b2[tid]; }
    if (tid < 2) { b3s[tid] = b3[tid]; }
    __syncthreads();

    const int b = blockIdx.x * WARPS + warp;
    if (b >= B) return;

    float* S = wmem + warp * WARP_FLTS;

    // ---- Load x (float4, coalesced), transpose into [c][t] ----
    {
        const float4* xb4 = (const float4*)(x + (size_t)b * (LFULL * CIN));
        #pragma unroll
        for (int it = 0; it < 4; it++) {
            int idx = (lane + it * 32);          // float4 index
            int t = idx >> 1, c = (idx & 1) * 4; // 8 ch => 2 float4 per t
            float4 v = xb4[idx];
            S[XS_OFF + (c + 0) * WROW + t] = v.x;
            S[XS_OFF + (c + 1) * WROW + t] = v.y;
            S[XS_OFF + (c + 2) * WROW + t] = v.z;
            S[XS_OFF + (c + 3) * WROW + t] = v.w;
        }
    }
    __syncwarp();

    // ---- conv layers: lane = (o, g); g owns a contiguous t-block ----
    // layer 1+2: OC=8, 4 blocks of 16 positions; layer 3: OC=2, 16 blocks of 4.
    {
        // conv1: in XS (valid t<64) -> H1 (Lout=61), relu
        const float* in = S + XS_OFF;
        float* outp = S + H1_OFF;
        int o = lane >> 2, g = lane & 3, t0 = g * 16;
        int count = 61 - t0; count = count > 16 ? 16 : (count < 0 ? 0 : count);
        int jmax = count + 3;
        float acc[16];
        #pragma unroll
        for (int tt = 0; tt < 16; tt++) acc[tt] = 0.0f;
        for (int i = 0; i < 8; i++) {
            float xv[19];
            #pragma unroll
            for (int j = 0; j < 19; j++)
                xv[j] = (j < jmax) ? in[i * WROW + t0 + j] : 0.0f;
            #pragma unroll
            for (int k = 0; k < 4; k++) {
                float wk = w1s[(i * 4 + k) * 8 + o];
                #pragma unroll
                for (int tt = 0; tt < 16; tt++)
                    acc[tt] = fmaf(xv[tt + k], wk, acc[tt]);
            }
        }
        float bo = b1s[o];
        #pragma unroll
        for (int tt = 0; tt < 16; tt++)
            if (tt < count) outp[o * WROW + t0 + tt] = fmaxf(acc[tt] + bo, 0.0f);
    }
    __syncwarp();
    {
        // conv2: H1 (valid t<61) -> H2 (Lout=58), relu
        const float* in = S + H1_OFF;
        float* outp = S + H2_OFF;
        int o = lane >> 2, g = lane & 3, t0 = g * 16;
        int count = 58 - t0; count = count > 16 ? 16 : (count < 0 ? 0 : count);
        int jmax = count + 3;
        float acc[16];
        #pragma unroll
        for (int tt = 0; tt < 16; tt++) acc[tt] = 0.0f;
        for (int i = 0; i < 8; i++) {
            float xv[19];
            #pragma unroll
            for (int j = 0; j < 19; j++)
                xv[j] = (j < jmax) ? in[i * WROW + t0 + j] : 0.0f;
            #pragma unroll
            for (int k = 0; k < 4; k++) {
                float wk = w2s[(i * 4 + k) * 8 + o];
                #pragma unroll
                for (int tt = 0; tt < 16; tt++)
                    acc[tt] = fmaf(xv[tt + k], wk, acc[tt]);
            }
        }
        float bo = b2s[o];
        #pragma unroll
        for (int tt = 0; tt < 16; tt++)
            if (tt < count) outp[o * WROW + t0 + tt] = fmaxf(acc[tt] + bo, 0.0f);
    }
    __syncwarp();
    {
        // conv3: H2 (valid t<58) -> H3 (Lout=55), NO relu
        const float* in = S + H2_OFF;
        float* outp = S + H3_OFF;
        int o = lane >> 4, g = lane & 15, t0 = g * 4;
        int count = 55 - t0; count = count > 4 ? 4 : (count < 0 ? 0 : count);
        int jmax = count + 3;
        float acc[4] = {0.f, 0.f, 0.f, 0.f};
        for (int i = 0; i < 8; i++) {
            float xv[7];
            #pragma unroll
            for (int j = 0; j < 7; j++)
                xv[j] = (j < jmax) ? in[i * WROW + t0 + j] : 0.0f;
            #pragma unroll
            for (int k = 0; k < 4; k++) {
                float wk = w3s[(i * 4 + k) * 2 + o];
                #pragma unroll
                for (int tt = 0; tt < 4; tt++)
                    acc[tt] = fmaf(xv[tt + k], wk, acc[tt]);
            }
        }
        float bo = b3s[o];
        #pragma unroll
        for (int tt = 0; tt < 4; tt++)
            if (tt < count) outp[o * 56 + t0 + tt] = acc[tt] + bo;
    }
    __syncwarp();

    // ---- sig1 endpoint (path[54]) captured BEFORE aliasing overwrites ----
    float sig1v = 0.0f;
    if (lane < CC) {
        if (lane < 8)       sig1v = S[XS_OFF + lane * WROW + 63];
        else if (lane == 8) sig1v = 1.0f;
        else                sig1v = S[H3_OFF + (lane - 9) * 56 + 54];
    }

    // ---- dx[t][c] into DXS (aliases H1/H2; reads only XS and H3) ----
    for (int idx = lane; idx < 55 * 11; idx += 32) {
        int t = idx / 11, c = idx - t * 11;
        float v;
        if (c < 8) {
            v = (t == 0) ? S[XS_OFF + c * WROW + 9]
                         : S[XS_OFF + c * WROW + 9 + t] - S[XS_OFF + c * WROW + 8 + t];
        } else if (c == 8) {
            v = (t == 0) ? 0.0f : (1.0f / 54.0f);
        } else {
            int o = c - 9;
            v = (t == 0) ? S[H3_OFF + o * 56]
                         : S[H3_OFF + o * 56 + t] - S[H3_OFF + o * 56 + t - 1];
        }
        S[DXS_OFF + t * 12 + c] = v;
    }
    __syncwarp();

    // ---- signature main loop (factored Chen) ----
    int ijm[4], im[4], jm[4];
    bool valid3 = (lane + 96) < CC2;
    #pragma unroll
    for (int m = 0; m < 4; m++) {
        int ij = lane + 32 * m;
        if (ij >= CC2) ij = 0;
        ijm[m] = ij; im[m] = ij / 11; jm[m] = ij - (ij / 11) * 11;
    }

    float s1i[4] = {0.f, 0.f, 0.f, 0.f};
    float s2[4]  = {0.f, 0.f, 0.f, 0.f};
    float s3[4][11];
    #pragma unroll
    for (int m = 0; m < 4; m++)
        #pragma unroll
        for (int k = 0; k < 11; k++) s3[m][k] = 0.0f;

    const float* dxbase = S + DXS_OFF;
    for (int t = 0; t < LO; t++) {
        const float* row = dxbase + t * 12;
        float4 q0 = *(const float4*)(row);
        float4 q1 = *(const float4*)(row + 4);
        float4 q2 = *(const float4*)(row + 8);
        float d[11] = {q0.x, q0.y, q0.z, q0.w, q1.x, q1.y, q1.z, q1.w,
                       q2.x, q2.y, q2.z};

        #pragma unroll
        for (int m = 0; m < 4; m++) {
            if (m < 3 || valid3) {
                float di = row[im[m]];
                float dj = row[jm[m]];
                float Mv = fmaf(dj, fmaf(1.0f / 6.0f, di, 0.5f * s1i[m]), s2[m]);
                s2[m]    = fmaf(dj, fmaf(0.5f, di, s1i[m]), s2[m]);
                s1i[m]  += di;
                #pragma unroll
                for (int k = 0; k < 11; k++)
                    s3[m][k] = fmaf(Mv, d[k], s3[m][k]);
            }
        }
    }

    // ---- scatter signature to shared (conflict-free), then coalesced head ----
    __syncwarp();
    float* sig = S + SIG_OFF;
    if (lane < CC) sig[lane] = sig1v;
    #pragma unroll
    for (int m = 0; m < 4; m++) {
        if (m < 3 || valid3) {
            int ij = ijm[m];
            sig[CC + ij] = s2[m];
            #pragma unroll
            for (int k = 0; k < 11; k++)
                sig[CC + CC2 + ij * 11 + k] = s3[m][k];
        }
    }
    __syncwarp();

    float acc[NSTOCK];
    #pragma unroll
    for (int s = 0; s < NSTOCK; s++) acc[s] = 0.0f;

    for (int c0 = lane; c0 < SIGCH; c0 += 32) {
        float v = sig[c0];
        #pragma unroll
        for (int s = 0; s < NSTOCK; s++)
            acc[s] = fmaf(v, __ldg(&Wl[s * SIGCH + c0]), acc[s]);
    }

    #pragma unroll
    for (int s = 0; s < NSTOCK; s++) {
        float v = acc[s];
        #pragma unroll
        for (int off = 16; off > 0; off >>= 1)
            v += __shfl_xor_sync(0xffffffffu, v, off);
        if (lane == 0)
            out[b * NSTOCK + s] = v + __ldg(&bl[s]);
    }
}

extern "C" void kernel_launch(void* const* d_in, const int* in_sizes, int n_in,
                              void* d_out, int out_size)
{
    const float* x  = (const float*)d_in[0];
    const float* W1 = (const float*)d_in[1];
    const float* b1 = (const float*)d_in[2];
    const float* W2 = (const float*)d_in[3];
    const float* b2 = (const float*)d_in[4];
    const float* W3 = (const float*)d_in[5];
    const float* b3 = (const float*)d_in[6];
    const float* Wl = (const float*)d_in[7];
    const float* bl = (const float*)d_in[8];
    float* out = (float*)d_out;

    int B = in_sizes[0] / (LFULL * CIN);   // 8192
    int blocks = (B + WARPS - 1) / WARPS;

    deepsig_kernel<<<blocks, NTHREADS>>>(x, W1, b1, W2, b2, W3, b3, Wl, bl, out, B);
}

// round 3
// speedup vs baseline: 1.8333x; 1.0212x over previous
#include <cuda_runtime.h>

// B=8192, L=64, Cin=8, KS=4, trunc=9, Lo=55, Caug=11, DEPTH=3
// sig = 11 + 121 + 1331 = 1463 channels; head 1463 -> 10
#define WARPS    4
#define NTHREADS (32 * WARPS)
#define LFULL    64
#define CIN      8
#define LO       55
#define CC       11
#define CC2      121
#define SIGCH    1463
#define SIGPAD   1472            // 23 * 64
#define NSTOCK   10

// per-warp shared region (floats), rows padded to 65 to avoid bank conflicts
#define WROW     65
#define XS_OFF   0               // x transposed [c][t], 8*65
#define H1_OFF   520             // conv1 out, 8*65
#define H2_OFF   1040            // conv2 out, 8*65
#define H3_OFF   1560            // conv3 out, 2*56
#define DXS_OFF  520             // aliases H1/H2 (dead after conv3), 55*12
#define SIG_OFF  0               // aliases XS/H1/H2 after main loop, 1472
#define WARP_FLTS 1680

__device__ float g_WlPad[NSTOCK * SIGPAD];

__global__ void wl_pad_kernel(const float* __restrict__ Wl)
{
    int idx = blockIdx.x * blockDim.x + threadIdx.x;
    if (idx < NSTOCK * SIGPAD) {
        int s = idx / SIGPAD, c = idx - s * SIGPAD;
        g_WlPad[idx] = (c < SIGCH) ? Wl[s * SIGCH + c] : 0.0f;
    }
}

__device__ __forceinline__ unsigned long long pack2(float lo, float hi)
{
    unsigned long long r;
    asm("mov.b64 %0, {%1, %2};" : "=l"(r) : "f"(lo), "f"(hi));
    return r;
}
__device__ __forceinline__ void unpack2(unsigned long long v, float& lo, float& hi)
{
    asm("mov.b64 {%0, %1}, %2;" : "=f"(lo), "=f"(hi) : "l"(v));
}
__device__ __forceinline__ void fma2(unsigned long long& d,
                                     unsigned long long a, unsigned long long b)
{
    asm("fma.rn.f32x2 %0, %1, %2, %0;" : "+l"(d) : "l"(a), "l"(b));
}

__global__ void __launch_bounds__(NTHREADS)
deepsig_kernel(const float* __restrict__ x,
               const float* __restrict__ W1, const float* __restrict__ b1,
               const float* __restrict__ W2, const float* __restrict__ b2,
               const float* __restrict__ W3, const float* __restrict__ b3,
               const float* __restrict__ bl,
               float* __restrict__ out, int B)
{
    __shared__ __align__(16) float wmem[WARPS * WARP_FLTS];
    __shared__ float w1s[256], w2s[256], w3s[64], b1s[8], b2s[8], b3s[2];

    const int tid  = threadIdx.x;
    const int warp = tid >> 5;
    const int lane = tid & 31;

    // Stage conv weights transposed: ws[(i*4+k)*OC + o] = W[o][i][k]
    for (int i = tid; i < 256; i += NTHREADS) {
        int o = i >> 5, r = i & 31;
        w1s[r * 8 + o] = W1[i];
        w2s[r * 8 + o] = W2[i];
    }
    for (int i = tid; i < 64; i += NTHREADS) {
        int o = i >> 5, r = i & 31;
        w3s[r * 2 + o] = W3[i];
    }
    if (tid < 8) { b1s[tid] = b1[tid]; b2s[tid] = b2[tid]; }
    if (tid < 2) { b3s[tid] = b3[tid]; }
    __syncthreads();

    const int b = blockIdx.x * WARPS + warp;
    if (b >= B) return;

    float* S = wmem + warp * WARP_FLTS;

    // ---- Load x (float4, coalesced), transpose into [c][t] ----
    {
        const float4* xb4 = (const float4*)(x + (size_t)b * (LFULL * CIN));
        #pragma unroll
        for (int it = 0; it < 4; it++) {
            int idx = (lane + it * 32);
            int t = idx >> 1, c = (idx & 1) * 4;
            float4 v = xb4[idx];
            S[XS_OFF + (c + 0) * WROW + t] = v.x;
            S[XS_OFF + (c + 1) * WROW + t] = v.y;
            S[XS_OFF + (c + 2) * WROW + t] = v.z;
            S[XS_OFF + (c + 3) * WROW + t] = v.w;
        }
    }
    __syncwarp();

    // ---- conv1 (relu): XS -> H1, Lout=61 ----
    {
        const float* in = S + XS_OFF;
        float* outp = S + H1_OFF;
        int o = lane >> 2, g = lane & 3, t0 = g * 16;
        int count = 61 - t0; count = count > 16 ? 16 : count;
        int jmax = count + 3;
        float acc[16];
        #pragma unroll
        for (int tt = 0; tt < 16; tt++) acc[tt] = 0.0f;
        for (int i = 0; i < 8; i++) {
            float xv[19];
            #pragma unroll
            for (int j = 0; j < 19; j++)
                xv[j] = (j < jmax) ? in[i * WROW + t0 + j] : 0.0f;
            #pragma unroll
            for (int k = 0; k < 4; k++) {
                float wk = w1s[(i * 4 + k) * 8 + o];
                #pragma unroll
                for (int tt = 0; tt < 16; tt++)
                    acc[tt] = fmaf(xv[tt + k], wk, acc[tt]);
            }
        }
        float bo = b1s[o];
        #pragma unroll
        for (int tt = 0; tt < 16; tt++)
            if (tt < count) outp[o * WROW + t0 + tt] = fmaxf(acc[tt] + bo, 0.0f);
    }
    __syncwarp();
    // ---- conv2 (relu): H1 -> H2, Lout=58 ----
    {
        const float* in = S + H1_OFF;
        float* outp = S + H2_OFF;
        int o = lane >> 2, g = lane & 3, t0 = g * 16;
        int count = 58 - t0; count = count > 16 ? 16 : count;
        int jmax = count + 3;
        float acc[16];
        #pragma unroll
        for (int tt = 0; tt < 16; tt++) acc[tt] = 0.0f;
        for (int i = 0; i < 8; i++) {
            float xv[19];
            #pragma unroll
            for (int j = 0; j < 19; j++)
                xv[j] = (j < jmax) ? in[i * WROW + t0 + j] : 0.0f;
            #pragma unroll
            for (int k = 0; k < 4; k++) {
                float wk = w2s[(i * 4 + k) * 8 + o];
                #pragma unroll
                for (int tt = 0; tt < 16; tt++)
                    acc[tt] = fmaf(xv[tt + k], wk, acc[tt]);
            }
        }
        float bo = b2s[o];
        #pragma unroll
        for (int tt = 0; tt < 16; tt++)
            if (tt < count) outp[o * WROW + t0 + tt] = fmaxf(acc[tt] + bo, 0.0f);
    }
    __syncwarp();
    // ---- conv3 (no relu): H2 -> H3, Lout=55 ----
    {
        const float* in = S + H2_OFF;
        float* outp = S + H3_OFF;
        int o = lane >> 4, g = lane & 15, t0 = g * 4;
        int count = 55 - t0; count = count > 4 ? 4 : (count < 0 ? 0 : count);
        int jmax = count + 3;
        float acc[4] = {0.f, 0.f, 0.f, 0.f};
        for (int i = 0; i < 8; i++) {
            float xv[7];
            #pragma unroll
            for (int j = 0; j < 7; j++)
                xv[j] = (j < jmax) ? in[i * WROW + t0 + j] : 0.0f;
            #pragma unroll
            for (int k = 0; k < 4; k++) {
                float wk = w3s[(i * 4 + k) * 2 + o];
                #pragma unroll
                for (int tt = 0; tt < 4; tt++)
                    acc[tt] = fmaf(xv[tt + k], wk, acc[tt]);
            }
        }
        float bo = b3s[o];
        #pragma unroll
        for (int tt = 0; tt < 4; tt++)
            if (tt < count) outp[o * 56 + t0 + tt] = acc[tt] + bo;
    }
    __syncwarp();

    // ---- sig1 endpoint captured before aliasing ----
    float sig1v = 0.0f;
    if (lane < CC) {
        if (lane < 8)       sig1v = S[XS_OFF + lane * WROW + 63];
        else if (lane == 8) sig1v = 1.0f;
        else                sig1v = S[H3_OFF + (lane - 9) * 56 + 54];
    }

    // ---- dx[t][c] (c=0..10, col 11 = 0 pad) into DXS ----
    for (int idx = lane; idx < 55 * 12; idx += 32) {
        int t = idx / 12, c = idx - t * 12;
        float v;
        if (c < 8) {
            v = (t == 0) ? S[XS_OFF + c * WROW + 9]
                         : S[XS_OFF + c * WROW + 9 + t] - S[XS_OFF + c * WROW + 8 + t];
        } else if (c == 8) {
            v = (t == 0) ? 0.0f : (1.0f / 54.0f);
        } else if (c < 11) {
            int o = c - 9;
            v = (t == 0) ? S[H3_OFF + o * 56]
                         : S[H3_OFF + o * 56 + t] - S[H3_OFF + o * 56 + t - 1];
        } else {
            v = 0.0f;   // pad column
        }
        S[DXS_OFF + idx] = v;
    }
    __syncwarp();

    // ---- signature main loop (factored Chen, packed f32x2) ----
    // slots ij = lane + 32m, ij in [0,128); ij>=121 are exact no-ops since
    // i=11 -> di = row[11] = 0 -> s1i stays 0, s2/s3 updates vanish.
    int im[4], jm[4];
    #pragma unroll
    for (int m = 0; m < 4; m++) {
        int ij = lane + 32 * m;
        im[m] = ij / 11; jm[m] = ij - im[m] * 11;
    }

    float s1i[4] = {0.f, 0.f, 0.f, 0.f};
    float s2[4]  = {0.f, 0.f, 0.f, 0.f};
    unsigned long long s3p[4][6];
    #pragma unroll
    for (int m = 0; m < 4; m++)
        #pragma unroll
        for (int q = 0; q < 6; q++) s3p[m][q] = 0ULL;

    const float* dxbase = S + DXS_OFF;
    for (int t = 0; t < LO; t++) {
        const float* row = dxbase + t * 12;
        ulonglong2 a0 = *(const ulonglong2*)(row);
        ulonglong2 a1 = *(const ulonglong2*)(row + 4);
        ulonglong2 a2 = *(const ulonglong2*)(row + 8);
        unsigned long long dp[6] = {a0.x, a0.y, a1.x, a1.y, a2.x, a2.y};

        #pragma unroll
        for (int m = 0; m < 4; m++) {
            float di = row[im[m]];
            float dj = row[jm[m]];
            float Mv = fmaf(dj, fmaf(1.0f / 6.0f, di, 0.5f * s1i[m]), s2[m]);
            s2[m]    = fmaf(dj, fmaf(0.5f, di, s1i[m]), s2[m]);
            s1i[m]  += di;
            unsigned long long mvp = pack2(Mv, Mv);
            #pragma unroll
            for (int q = 0; q < 6; q++)
                fma2(s3p[m][q], dp[q], mvp);
        }
    }

    // ---- scatter signature to shared (conflict-free) ----
    __syncwarp();
    float* sig = S + SIG_OFF;
    if (lane < CC) sig[lane] = sig1v;
    if (lane < SIGPAD - SIGCH) sig[SIGCH + lane] = 0.0f;  // pad tail
    #pragma unroll
    for (int m = 0; m < 4; m++) {
        int ij = lane + 32 * m;
        if (ij < CC2) {
            sig[CC + ij] = s2[m];
            #pragma unroll
            for (int q = 0; q < 6; q++) {
                float lo, hi;
                unpack2(s3p[m][q], lo, hi);
                int k = 2 * q;
                sig[CC + CC2 + ij * 11 + k] = lo;
                if (k + 1 < 11) sig[CC + CC2 + ij * 11 + k + 1] = hi;
            }
        }
    }
    __syncwarp();

    // ---- fused head: 2 channels/lane/iter, packed FFMA2 ----
    unsigned long long accp[NSTOCK];
    #pragma unroll
    for (int s = 0; s < NSTOCK; s++) accp[s] = 0ULL;

    const float* wl = g_WlPad;
    for (int it = 0; it < SIGPAD / 64; it++) {
        int c = 2 * lane + 64 * it;
        unsigned long long vp = *(const unsigned long long*)(sig + c);
        #pragma unroll
        for (int s = 0; s < NSTOCK; s++) {
            unsigned long long wp =
                *(const unsigned long long*)(wl + s * SIGPAD + c);
            fma2(accp[s], vp, wp);
        }
    }

    #pragma unroll
    for (int s = 0; s < NSTOCK; s++) {
        float lo, hi;
        unpack2(accp[s], lo, hi);
        float v = lo + hi;
        #pragma unroll
        for (int off = 16; off > 0; off >>= 1)
            v += __shfl_xor_sync(0xffffffffu, v, off);
        if (lane == 0)
            out[b * NSTOCK + s] = v + __ldg(&bl[s]);
    }
}

extern "C" void kernel_launch(void* const* d_in, const int* in_sizes, int n_in,
                              void* d_out, int out_size)
{
    const float* x  = (const float*)d_in[0];
    const float* W1 = (const float*)d_in[1];
    const float* b1 = (const float*)d_in[2];
    const float* W2 = (const float*)d_in[3];
    const float* b2 = (const float*)d_in[4];
    const float* W3 = (const float*)d_in[5];
    const float* b3 = (const float*)d_in[6];
    const float* Wl = (const float*)d_in[7];
    const float* bl = (const float*)d_in[8];
    float* out = (float*)d_out;

    int B = in_sizes[0] / (LFULL * CIN);   // 8192

    wl_pad_kernel<<<(NSTOCK * SIGPAD + 255) / 256, 256>>>(Wl);

    int blocks = (B + WARPS - 1) / WARPS;
    deepsig_kernel<<<blocks, NTHREADS>>>(x, W1, b1, W2, b2, W3, b3, bl, out, B);
}

// round 4
// speedup vs baseline: 1.8717x; 1.0209x over previous
#include <cuda_runtime.h>

// B=8192, L=64, Cin=8, KS=4, trunc=9, Lo=55, Caug=11, DEPTH=3
// sig = 11 + 121 + 1331 = 1463 channels; head 1463 -> 10
#define WARPS    4
#define NTHREADS (32 * WARPS)
#define LFULL    64
#define CIN      8
#define LO       55
#define CC       11
#define CC2      121
#define SIGCH    1463
#define SIGPAD   1472            // 23 * 64
#define NSTOCK   10

// per-warp shared region (floats); rows pitched 68 (16B-aligned float4 rows)
#define WROW     68
#define XS_OFF   0               // x transposed [c][t], 8*68
#define H1_OFF   544             // conv1 out, 8*68
#define H2_OFF   1088            // conv2 out, 8*68
#define H3_OFF   1632            // conv3 out, 2*56
#define DXS_OFF  544             // aliases H1/H2 (dead after conv3), 55*12
#define SIG_OFF  0               // aliases XS/H1/DXS after main loop, 1472
#define WARP_FLTS 1744           // bytes = 6976, 16B aligned

__device__ float g_WlPad[NSTOCK * SIGPAD];

__global__ void wl_pad_kernel(const float* __restrict__ Wl)
{
    int idx = blockIdx.x * blockDim.x + threadIdx.x;
    if (idx < NSTOCK * SIGPAD) {
        int s = idx / SIGPAD, c = idx - s * SIGPAD;
        g_WlPad[idx] = (c < SIGCH) ? Wl[s * SIGCH + c] : 0.0f;
    }
}

__device__ __forceinline__ unsigned long long pack2(float lo, float hi)
{
    unsigned long long r;
    asm("mov.b64 %0, {%1, %2};" : "=l"(r) : "f"(lo), "f"(hi));
    return r;
}
__device__ __forceinline__ void unpack2(unsigned long long v, float& lo, float& hi)
{
    asm("mov.b64 {%0, %1}, %2;" : "=f"(lo), "=f"(hi) : "l"(v));
}
__device__ __forceinline__ void fma2(unsigned long long& d,
                                     unsigned long long a, unsigned long long b)
{
    asm("fma.rn.f32x2 %0, %1, %2, %0;" : "+l"(d) : "l"(a), "l"(b));
}

__global__ void __launch_bounds__(NTHREADS)
deepsig_kernel(const float* __restrict__ x,
               const float* __restrict__ W1, const float* __restrict__ b1,
               const float* __restrict__ W2, const float* __restrict__ b2,
               const float* __restrict__ W3, const float* __restrict__ b3,
               const float* __restrict__ bl,
               float* __restrict__ out, int B)
{
    __shared__ __align__(16) float wmem[WARPS * WARP_FLTS];
    __shared__ float w1s[256], w2s[256], w3s[64], b1s[8], b2s[8], b3s[2];

    const int tid  = threadIdx.x;
    const int warp = tid >> 5;
    const int lane = tid & 31;

    // Stage conv weights transposed: ws[(i*4+k)*OC + o] = W[o][i][k]
    for (int i = tid; i < 256; i += NTHREADS) {
        int o = i >> 5, r = i & 31;
        w1s[r * 8 + o] = W1[i];
        w2s[r * 8 + o] = W2[i];
    }
    for (int i = tid; i < 64; i += NTHREADS) {
        int o = i >> 5, r = i & 31;
        w3s[r * 2 + o] = W3[i];
    }
    if (tid < 8) { b1s[tid] = b1[tid]; b2s[tid] = b2[tid]; }
    if (tid < 2) { b3s[tid] = b3[tid]; }
    __syncthreads();

    const int b = blockIdx.x * WARPS + warp;
    const bool bvalid = (b < B);

    float* S = wmem + warp * WARP_FLTS;

    if (bvalid) {
        // ---- Load x (float4, coalesced), transpose into [c][t] pitch 68 ----
        const float4* xb4 = (const float4*)(x + (size_t)b * (LFULL * CIN));
        #pragma unroll
        for (int it = 0; it < 4; it++) {
            int idx = (lane + it * 32);
            int t = idx >> 1, c = (idx & 1) * 4;
            float4 v = xb4[idx];
            S[XS_OFF + (c + 0) * WROW + t] = v.x;
            S[XS_OFF + (c + 1) * WROW + t] = v.y;
            S[XS_OFF + (c + 2) * WROW + t] = v.z;
            S[XS_OFF + (c + 3) * WROW + t] = v.w;
        }
        __syncwarp();

        // ---- conv1 (relu): XS -> H1, Lout=61; window = 5x LDS.128 ----
        {
            const float* in = S + XS_OFF;
            float* outp = S + H1_OFF;
            int o = lane >> 2, g = lane & 3, t0 = g * 16;
            int count = 61 - t0; if (count > 16) count = 16;
            float acc[16];
            #pragma unroll
            for (int tt = 0; tt < 16; tt++) acc[tt] = 0.0f;
            for (int i = 0; i < 8; i++) {
                float xv[20];
                const float4* p = (const float4*)(in + i * WROW + t0);
                #pragma unroll
                for (int q = 0; q < 5; q++) {
                    float4 v = p[q];
                    xv[4*q+0] = v.x; xv[4*q+1] = v.y;
                    xv[4*q+2] = v.z; xv[4*q+3] = v.w;
                }
                #pragma unroll
                for (int k = 0; k < 4; k++) {
                    float wk = w1s[(i * 4 + k) * 8 + o];
                    #pragma unroll
                    for (int tt = 0; tt < 16; tt++)
                        acc[tt] = fmaf(xv[tt + k], wk, acc[tt]);
                }
            }
            float bo = b1s[o];
            #pragma unroll
            for (int tt = 0; tt < 16; tt++)
                if (tt < count) outp[o * WROW + t0 + tt] = fmaxf(acc[tt] + bo, 0.0f);
        }
        __syncwarp();
        // ---- conv2 (relu): H1 -> H2, Lout=58 ----
        {
            const float* in = S + H1_OFF;
            float* outp = S + H2_OFF;
            int o = lane >> 2, g = lane & 3, t0 = g * 16;
            int count = 58 - t0; if (count > 16) count = 16;
            float acc[16];
            #pragma unroll
            for (int tt = 0; tt < 16; tt++) acc[tt] = 0.0f;
            for (int i = 0; i < 8; i++) {
                float xv[20];
                const float4* p = (const float4*)(in + i * WROW + t0);
                #pragma unroll
                for (int q = 0; q < 5; q++) {
                    float4 v = p[q];
                    xv[4*q+0] = v.x; xv[4*q+1] = v.y;
                    xv[4*q+2] = v.z; xv[4*q+3] = v.w;
                }
                #pragma unroll
                for (int k = 0; k < 4; k++) {
                    float wk = w2s[(i * 4 + k) * 8 + o];
                    #pragma unroll
                    for (int tt = 0; tt < 16; tt++)
                        acc[tt] = fmaf(xv[tt + k], wk, acc[tt]);
                }
            }
            float bo = b2s[o];
            #pragma unroll
            for (int tt = 0; tt < 16; tt++)
                if (tt < count) outp[o * WROW + t0 + tt] = fmaxf(acc[tt] + bo, 0.0f);
        }
        __syncwarp();
        // ---- conv3 (no relu): H2 -> H3, Lout=55; window = 2x LDS.128 ----
        {
            const float* in = S + H2_OFF;
            float* outp = S + H3_OFF;
            int o = lane >> 4, g = lane & 15, t0 = g * 4;
            int count = 55 - t0; count = count > 4 ? 4 : (count < 0 ? 0 : count);
            float acc[4] = {0.f, 0.f, 0.f, 0.f};
            for (int i = 0; i < 8; i++) {
                float xv[8];
                const float4* p = (const float4*)(in + i * WROW + t0);
                #pragma unroll
                for (int q = 0; q < 2; q++) {
                    float4 v = p[q];
                    xv[4*q+0] = v.x; xv[4*q+1] = v.y;
                    xv[4*q+2] = v.z; xv[4*q+3] = v.w;
                }
                #pragma unroll
                for (int k = 0; k < 4; k++) {
                    float wk = w3s[(i * 4 + k) * 2 + o];
                    #pragma unroll
                    for (int tt = 0; tt < 4; tt++)
                        acc[tt] = fmaf(xv[tt + k], wk, acc[tt]);
                }
            }
            float bo = b3s[o];
            #pragma unroll
            for (int tt = 0; tt < 4; tt++)
                if (tt < count) outp[o * 56 + t0 + tt] = acc[tt] + bo;
        }
        __syncwarp();
    }

    // ---- sig1 endpoint captured before aliasing ----
    float sig1v = 0.0f;
    if (bvalid && lane < CC) {
        if (lane < 8)       sig1v = S[XS_OFF + lane * WROW + 63];
        else if (lane == 8) sig1v = 1.0f;
        else                sig1v = S[H3_OFF + (lane - 9) * 56 + 54];
    }

    // slot geometry
    int im[4], jm[4];
    #pragma unroll
    for (int m = 0; m < 4; m++) {
        int ij = lane + 32 * m;
        im[m] = ij / 11; jm[m] = ij - im[m] * 11;
    }
    float s1i[4] = {0.f, 0.f, 0.f, 0.f};
    float s2[4]  = {0.f, 0.f, 0.f, 0.f};
    unsigned long long s3p[4][6];
    #pragma unroll
    for (int m = 0; m < 4; m++)
        #pragma unroll
        for (int q = 0; q < 6; q++) s3p[m][q] = 0ULL;

    if (bvalid) {
        // ---- dx[t][c] (c=0..10, col 11 = 0 pad) into DXS ----
        for (int idx = lane; idx < 55 * 12; idx += 32) {
            int t = idx / 12, c = idx - t * 12;
            float v;
            if (c < 8) {
                v = (t == 0) ? S[XS_OFF + c * WROW + 9]
                             : S[XS_OFF + c * WROW + 9 + t] - S[XS_OFF + c * WROW + 8 + t];
            } else if (c == 8) {
                v = (t == 0) ? 0.0f : (1.0f / 54.0f);
            } else if (c < 11) {
                int o = c - 9;
                v = (t == 0) ? S[H3_OFF + o * 56]
                             : S[H3_OFF + o * 56 + t] - S[H3_OFF + o * 56 + t - 1];
            } else {
                v = 0.0f;
            }
            S[DXS_OFF + idx] = v;
        }
        __syncwarp();

        // ---- signature main loop (factored Chen, packed f32x2) ----
        // ij >= 121 are exact no-ops (di = pad 0)
        const float* dxbase = S + DXS_OFF;
        for (int t = 0; t < LO; t++) {
            const float* row = dxbase + t * 12;
            ulonglong2 a0 = *(const ulonglong2*)(row);
            ulonglong2 a1 = *(const ulonglong2*)(row + 4);
            ulonglong2 a2 = *(const ulonglong2*)(row + 8);
            unsigned long long dp[6] = {a0.x, a0.y, a1.x, a1.y, a2.x, a2.y};

            #pragma unroll
            for (int m = 0; m < 4; m++) {
                float di = row[im[m]];
                float dj = row[jm[m]];
                float Mv = fmaf(dj, fmaf(1.0f / 6.0f, di, 0.5f * s1i[m]), s2[m]);
                s2[m]    = fmaf(dj, fmaf(0.5f, di, s1i[m]), s2[m]);
                s1i[m]  += di;
                unsigned long long mvp = pack2(Mv, Mv);
                #pragma unroll
                for (int q = 0; q < 6; q++)
                    fma2(s3p[m][q], dp[q], mvp);
            }
        }
        __syncwarp();

        // ---- scatter signature to shared (conflict-free) ----
        float* sig = S + SIG_OFF;
        if (lane < CC) sig[lane] = sig1v;
        if (lane < SIGPAD - SIGCH) sig[SIGCH + lane] = 0.0f;
        #pragma unroll
        for (int m = 0; m < 4; m++) {
            int ij = lane + 32 * m;
            if (ij < CC2) {
                sig[CC + ij] = s2[m];
                #pragma unroll
                for (int q = 0; q < 6; q++) {
                    float lo, hi;
                    unpack2(s3p[m][q], lo, hi);
                    int k = 2 * q;
                    sig[CC + CC2 + ij * 11 + k] = lo;
                    if (k + 1 < 11) sig[CC + CC2 + ij * 11 + k + 1] = hi;
                }
            }
        }
    }
    __syncthreads();

    // ---- block-cooperative head: warps split stocks {3,3,2,2}; each warp
    //      applies its stocks' weights to ALL 4 batch sigs (Wl read once) ----
    const int s_base = (warp < 2) ? warp * 3 : 6 + (warp - 2) * 2;
    const int n_s    = (warp < 2) ? 3 : 2;

    unsigned long long acc[4][3];
    #pragma unroll
    for (int bb = 0; bb < 4; bb++)
        #pragma unroll
        for (int sl = 0; sl < 3; sl++) acc[bb][sl] = 0ULL;

    const float* wl = g_WlPad;
    for (int it = 0; it < SIGPAD / 64; it++) {
        int c = 2 * lane + 64 * it;
        unsigned long long vp[4];
        #pragma unroll
        for (int bb = 0; bb < 4; bb++)
            vp[bb] = *(const unsigned long long*)(wmem + bb * WARP_FLTS + SIG_OFF + c);
        #pragma unroll
        for (int sl = 0; sl < 3; sl++) {
            if (sl < n_s) {
                unsigned long long wp =
                    *(const unsigned long long*)(wl + (s_base + sl) * SIGPAD + c);
                #pragma unroll
                for (int bb = 0; bb < 4; bb++)
                    fma2(acc[bb][sl], vp[bb], wp);
            }
        }
    }

    #pragma unroll
    for (int bb = 0; bb < 4; bb++) {
        int bg = blockIdx.x * WARPS + bb;
        #pragma unroll
        for (int sl = 0; sl < 3; sl++) {
            if (sl < n_s) {
                float lo, hi;
                unpack2(acc[bb][sl], lo, hi);
                float v = lo + hi;
                #pragma unroll
                for (int off = 16; off > 0; off >>= 1)
                    v += __shfl_xor_sync(0xffffffffu, v, off);
                if (lane == 0 && bg < B)
                    out[bg * NSTOCK + s_base + sl] = v + __ldg(&bl[s_base + sl]);
            }
        }
    }
}

extern "C" void kernel_launch(void* const* d_in, const int* in_sizes, int n_in,
                              void* d_out, int out_size)
{
    const float* x  = (const float*)d_in[0];
    const float* W1 = (const float*)d_in[1];
    const float* b1 = (const float*)d_in[2];
    const float* W2 = (const float*)d_in[3];
    const float* b2 = (const float*)d_in[4];
    const float* W3 = (const float*)d_in[5];
    const float* b3 = (const float*)d_in[6];
    const float* Wl = (const float*)d_in[7];
    const float* bl = (const float*)d_in[8];
    float* out = (float*)d_out;

    int B = in_sizes[0] / (LFULL * CIN);   // 8192

    wl_pad_kernel<<<(NSTOCK * SIGPAD + 255) / 256, 256>>>(Wl);

    int blocks = (B + WARPS - 1) / WARPS;
    deepsig_kernel<<<blocks, NTHREADS>>>(x, W1, b1, W2, b2, W3, b3, bl, out, B);
}